// round 1
// baseline (speedup 1.0000x reference)
#include <cuda_runtime.h>
#include <cstdint>

// ---------------------------------------------------------------------------
// MeshRefineNet: 4x GraphConv (pytorch3d-style) on GB300.
//   layer i: h0 = x@W0+b0; h1 = x@W1+b1; out = h0 + scatter_add(h1 over edges)
//   relu after layers 0..2; skip (x += features) before layer 3; layer 3 dout=3.
// N = 320000 nodes, F = 128, E = 960000 undirected edges.
// ---------------------------------------------------------------------------

#define NMAX 320000

// Scratch (allocation-free rule: __device__ globals)
__device__ float g_bufA[NMAX * 128];
__device__ float g_bufB[NMAX * 128];
__device__ float g_h1 [NMAX * 128];
__device__ float g_h1s[NMAX * 3];

// ---- packed f32x2 helpers (B300: FFMA rt=2/SMSP, f32x2 doubles fp32 rate) ----
__device__ __forceinline__ unsigned long long pk2(float lo, float hi) {
    unsigned long long r;
    asm("mov.b64 %0, {%1, %2};" : "=l"(r) : "f"(lo), "f"(hi));
    return r;
}
__device__ __forceinline__ float2 upk2(unsigned long long v) {
    float2 r;
    asm("mov.b64 {%0, %1}, %2;" : "=f"(r.x), "=f"(r.y) : "l"(v));
    return r;
}
__device__ __forceinline__ void ffma2(unsigned long long& d,
                                      unsigned long long a,
                                      unsigned long long b) {
    asm("fma.rn.f32x2 %0, %1, %2, %0;" : "+l"(d) : "l"(a), "l"(b));
}

// ---------------------------------------------------------------------------
// Fused dual-GEMM: out_agg = x@W0+b0 (seed for scatter), out_h1 = x@W1+b1.
// M-tile 64, N = 256 (h0|h1 concat), K = 128 in BK=16 steps.
// 256 threads, each owns an 8x8 microtile split as rows {ty*4+r, 32+ty*4+r},
// cols {tx*4+c, 128+tx*4+c}; accumulators are packed f32x2 pairs.
// MODE: 0 = raw input, 1 = relu(input) fused into the A-tile load.
// ---------------------------------------------------------------------------
template<int MODE>
__global__ __launch_bounds__(256, 2)
void gemm256_kernel(const float* __restrict__ in,
                    const float* __restrict__ W0, const float* __restrict__ b0,
                    const float* __restrict__ W1, const float* __restrict__ b1,
                    float* __restrict__ agg, float* __restrict__ h1, int n)
{
    constexpr int BM = 64, BK = 16;
    __shared__ float As[BK][BM];       // transposed A tile
    __shared__ float Bs[BK][256];      // [k][j], j<128 from W0, j>=128 from W1
    __shared__ float biasS[256];

    const int tid = threadIdx.x;
    const int m0  = blockIdx.x * BM;

    biasS[tid] = (tid < 128) ? __ldg(&b0[tid]) : __ldg(&b1[tid - 128]);

    const int tx = tid & 31;
    const int ty = tid >> 5;

    unsigned long long acc[2][4][2][2];
#pragma unroll
    for (int a = 0; a < 2; a++)
#pragma unroll
        for (int r = 0; r < 4; r++)
#pragma unroll
            for (int c = 0; c < 2; c++)
#pragma unroll
                for (int p = 0; p < 2; p++) acc[a][r][c][p] = 0ull;

    const int anode = tid >> 2;          // 0..63
    const int akq   = (tid & 3) * 4;     // k offset within BK
    const int gnode = m0 + anode;

    for (int k0 = 0; k0 < 128; k0 += BK) {
        // stage A (with fused relu)
        float4 av = make_float4(0.f, 0.f, 0.f, 0.f);
        if (gnode < n) {
            av = *(const float4*)(in + (size_t)gnode * 128 + k0 + akq);
            if (MODE == 1) {
                av.x = fmaxf(av.x, 0.f); av.y = fmaxf(av.y, 0.f);
                av.z = fmaxf(av.z, 0.f); av.w = fmaxf(av.w, 0.f);
            }
        }
        // stage B: 4 float4 per thread, coalesced rows of W0/W1
        float4 bv[4];
#pragma unroll
        for (int s = 0; s < 4; s++) {
            int idx = s * 256 + tid;
            int row = idx >> 6;            // 0..15
            int j   = (idx & 63) * 4;      // 0..252
            const float* wsrc = (j < 128)
                ? (W0 + (size_t)(k0 + row) * 128 + j)
                : (W1 + (size_t)(k0 + row) * 128 + (j - 128));
            bv[s] = *(const float4*)wsrc;
        }
        __syncthreads();   // previous iteration's compute done
        As[akq + 0][anode] = av.x;
        As[akq + 1][anode] = av.y;
        As[akq + 2][anode] = av.z;
        As[akq + 3][anode] = av.w;
#pragma unroll
        for (int s = 0; s < 4; s++) {
            int idx = s * 256 + tid;
            int row = idx >> 6;
            int j   = (idx & 63) * 4;
            *(float4*)&Bs[row][j] = bv[s];
        }
        __syncthreads();

#pragma unroll
        for (int kk = 0; kk < BK; kk++) {
            float4 a0 = *(float4*)&As[kk][ty * 4];        // broadcast
            float4 a1 = *(float4*)&As[kk][32 + ty * 4];   // broadcast
            ulonglong2 bb0 = *(ulonglong2*)&Bs[kk][tx * 4];        // h0 cols
            ulonglong2 bb1 = *(ulonglong2*)&Bs[kk][128 + tx * 4];  // h1 cols
            float ar0[4] = {a0.x, a0.y, a0.z, a0.w};
            float ar1[4] = {a1.x, a1.y, a1.z, a1.w};
#pragma unroll
            for (int r = 0; r < 4; r++) {
                unsigned long long d0 = pk2(ar0[r], ar0[r]);
                ffma2(acc[0][r][0][0], d0, bb0.x);
                ffma2(acc[0][r][0][1], d0, bb0.y);
                ffma2(acc[0][r][1][0], d0, bb1.x);
                ffma2(acc[0][r][1][1], d0, bb1.y);
                unsigned long long d1 = pk2(ar1[r], ar1[r]);
                ffma2(acc[1][r][0][0], d1, bb0.x);
                ffma2(acc[1][r][0][1], d1, bb0.y);
                ffma2(acc[1][r][1][0], d1, bb1.x);
                ffma2(acc[1][r][1][1], d1, bb1.y);
            }
        }
    }

    // epilogue: +bias, write h0 -> agg (seed), h1 -> h1 buffer
    float4 bias0 = *(float4*)&biasS[tx * 4];
    float4 bias1 = *(float4*)&biasS[128 + tx * 4];
#pragma unroll
    for (int rh = 0; rh < 2; rh++) {
#pragma unroll
        for (int r = 0; r < 4; r++) {
            int gm = m0 + rh * 32 + ty * 4 + r;
            if (gm < n) {
                float2 p0 = upk2(acc[rh][r][0][0]);
                float2 p1 = upk2(acc[rh][r][0][1]);
                float4 v0 = make_float4(p0.x + bias0.x, p0.y + bias0.y,
                                        p1.x + bias0.z, p1.y + bias0.w);
                *(float4*)(agg + (size_t)gm * 128 + tx * 4) = v0;
                float2 q0 = upk2(acc[rh][r][1][0]);
                float2 q1 = upk2(acc[rh][r][1][1]);
                float4 v1 = make_float4(q0.x + bias1.x, q0.y + bias1.y,
                                        q1.x + bias1.z, q1.y + bias1.w);
                *(float4*)(h1 + (size_t)gm * 128 + tx * 4) = v1;
            }
        }
    }
}

// ---------------------------------------------------------------------------
// Edge scatter for 128-wide features: one warp per edge, both directions.
// Lane l handles floats {l, l+32, l+64, l+96}: every LDG/RED instruction is a
// dense 128B line. agg already holds h0, atomics add the neighbor sum.
// ---------------------------------------------------------------------------
__global__ void scatter128_kernel(const int2* __restrict__ edges,
                                  const float* __restrict__ h1,
                                  float* __restrict__ agg, int E)
{
    int w = (int)((blockIdx.x * (unsigned)blockDim.x + threadIdx.x) >> 5);
    int lane = threadIdx.x & 31;
    if (w >= E) return;
    int2 e = __ldg(&edges[w]);
    const float* hs = h1 + (size_t)e.x * 128;
    const float* hd = h1 + (size_t)e.y * 128;
    float* as_ = agg + (size_t)e.x * 128;
    float* ad_ = agg + (size_t)e.y * 128;
#pragma unroll
    for (int f = 0; f < 4; f++) {
        int o = f * 32 + lane;
        atomicAdd(as_ + o, hd[o]);   // agg[src] += h1[dst]
    }
#pragma unroll
    for (int f = 0; f < 4; f++) {
        int o = f * 32 + lane;
        atomicAdd(ad_ + o, hs[o]);   // agg[dst] += h1[src]
    }
}

// ---------------------------------------------------------------------------
// Final layer (dout=3): x = relu(in) + features (fused skip), h0 -> d_out,
// h1 -> g_h1s. One warp per node; warp-reduce the 6 dot products.
// ---------------------------------------------------------------------------
__global__ __launch_bounds__(256)
void final_kernel(const float* __restrict__ in, const float* __restrict__ feat,
                  const float* __restrict__ W0, const float* __restrict__ b0,
                  const float* __restrict__ W1, const float* __restrict__ b1,
                  float* __restrict__ out, float* __restrict__ h1s, int n)
{
    __shared__ float ws[128][6];
    __shared__ float bs[6];
    int tid = threadIdx.x;
    for (int idx = tid; idx < 768; idx += 256) {
        int k = idx / 6, j = idx % 6;
        ws[k][j] = (j < 3) ? __ldg(&W0[k * 3 + j]) : __ldg(&W1[k * 3 + (j - 3)]);
    }
    if (tid < 3)      bs[tid] = __ldg(&b0[tid]);
    else if (tid < 6) bs[tid] = __ldg(&b1[tid - 3]);
    __syncthreads();

    int lane = tid & 31;
    int node = blockIdx.x * 8 + (tid >> 5);
    if (node >= n) return;

    float acc[6] = {0.f, 0.f, 0.f, 0.f, 0.f, 0.f};
    const float* xin = in   + (size_t)node * 128;
    const float* xf  = feat + (size_t)node * 128;
#pragma unroll
    for (int f = 0; f < 4; f++) {
        int k = f * 32 + lane;
        float x = fmaxf(xin[k], 0.f) + xf[k];
#pragma unroll
        for (int j = 0; j < 6; j++) acc[j] += x * ws[k][j];
    }
#pragma unroll
    for (int j = 0; j < 6; j++) {
#pragma unroll
        for (int o = 16; o > 0; o >>= 1)
            acc[j] += __shfl_xor_sync(0xffffffffu, acc[j], o);
    }
    if (lane == 0) {
        out[node * 3 + 0] = acc[0] + bs[0];
        out[node * 3 + 1] = acc[1] + bs[1];
        out[node * 3 + 2] = acc[2] + bs[2];
        h1s[node * 3 + 0] = acc[3] + bs[3];
        h1s[node * 3 + 1] = acc[4] + bs[4];
        h1s[node * 3 + 2] = acc[5] + bs[5];
    }
}

// Final scatter (3-wide): one thread per edge, both directions.
__global__ void scatter3_kernel(const int2* __restrict__ edges,
                                const float* __restrict__ h1s,
                                float* __restrict__ out, int E)
{
    int t = blockIdx.x * blockDim.x + threadIdx.x;
    if (t >= E) return;
    int2 e = __ldg(&edges[t]);
    size_t s = (size_t)e.x * 3, d = (size_t)e.y * 3;
    float hs0 = h1s[s + 0], hs1 = h1s[s + 1], hs2 = h1s[s + 2];
    float hd0 = h1s[d + 0], hd1 = h1s[d + 1], hd2 = h1s[d + 2];
    atomicAdd(out + s + 0, hd0);
    atomicAdd(out + s + 1, hd1);
    atomicAdd(out + s + 2, hd2);
    atomicAdd(out + d + 0, hs0);
    atomicAdd(out + d + 1, hs1);
    atomicAdd(out + d + 2, hs2);
}

// ---------------------------------------------------------------------------
// Launch: layer0 (raw) -> scatter -> layer1 (relu) -> scatter ->
//         layer2 (relu) -> scatter -> final (relu+skip, dout=3) -> scatter3
// ---------------------------------------------------------------------------
extern "C" void kernel_launch(void* const* d_in, const int* in_sizes, int n_in,
                              void* d_out, int out_size)
{
    const float* feat  = (const float*)d_in[0];
    const int2*  edges = (const int2*) d_in[1];
    const int N = in_sizes[0] / 128;
    const int E = in_sizes[1] / 2;

    const float *W0[4], *B0[4], *W1[4], *B1[4];
    for (int i = 0; i < 4; i++) {
        W0[i] = (const float*)d_in[2 + 4 * i];
        B0[i] = (const float*)d_in[3 + 4 * i];
        W1[i] = (const float*)d_in[4 + 4 * i];
        B1[i] = (const float*)d_in[5 + 4 * i];
    }

    float *bufA, *bufB, *h1, *h1s;
    cudaGetSymbolAddress((void**)&bufA, g_bufA);
    cudaGetSymbolAddress((void**)&bufB, g_bufB);
    cudaGetSymbolAddress((void**)&h1,   g_h1);
    cudaGetSymbolAddress((void**)&h1s,  g_h1s);

    const int gBlocks = (N + 63) / 64;
    const int sBlocks = (E + 7) / 8;          // 8 warps/block, warp per edge
    float* out = (float*)d_out;

    gemm256_kernel<0><<<gBlocks, 256>>>(feat, W0[0], B0[0], W1[0], B1[0], bufA, h1, N);
    scatter128_kernel<<<sBlocks, 256>>>(edges, h1, bufA, E);

    gemm256_kernel<1><<<gBlocks, 256>>>(bufA, W0[1], B0[1], W1[1], B1[1], bufB, h1, N);
    scatter128_kernel<<<sBlocks, 256>>>(edges, h1, bufB, E);

    gemm256_kernel<1><<<gBlocks, 256>>>(bufB, W0[2], B0[2], W1[2], B1[2], bufA, h1, N);
    scatter128_kernel<<<sBlocks, 256>>>(edges, h1, bufA, E);

    final_kernel<<<(N + 7) / 8, 256>>>(bufA, feat, W0[3], B0[3], W1[3], B1[3], out, h1s, N);
    scatter3_kernel<<<(E + 255) / 256, 256>>>(edges, h1s, out, E);
}